// round 2
// baseline (speedup 1.0000x reference)
#include <cuda_runtime.h>
#include <math.h>

#define B_   2
#define S_   2048
#define H_   16
#define DH_  64
#define DM_  1024
#define MTOK (B_ * S_)        // 4096

// ---------------- scratch (no allocations allowed) ----------------
__device__ float g_qkv[(size_t)MTOK * 3 * DM_];   // 48 MB
__device__ float g_q  [(size_t)B_ * H_ * S_ * DH_]; // 16 MB
__device__ float g_k  [(size_t)B_ * H_ * S_ * DH_];
__device__ float g_v  [(size_t)B_ * H_ * S_ * DH_];
__device__ float g_ao [(size_t)MTOK * DM_];        // 16 MB

// ---------------- SGEMM: C[m,n] = sum_k A[m,k] * B[n,k] ----------------
// A: [M,K] row-major, B: [N,K] row-major (both K-contiguous), C: [M,N].
// BM=BN=128, BK=16, 256 threads, 8x8 per thread.
template<int BM, int BN, int BK, int TM, int TN>
__device__ __forceinline__ void gemm_tn(const float* __restrict__ A,
                                        const float* __restrict__ Bw,
                                        float* __restrict__ C,
                                        int M, int N, int K)
{
    __shared__ float As[BK][BM];
    __shared__ float Bs[BK][BN];

    const int tid = threadIdx.x;            // 0..255
    const int bm  = blockIdx.y * BM;
    const int bn  = blockIdx.x * BN;

    const int lrow = tid >> 2;              // 0..63
    const int lcol = (tid & 3) << 2;        // 0,4,8,12
    const int tx   = tid & 15;              // 0..15
    const int ty   = tid >> 4;              // 0..15

    float acc[TM][TN];
#pragma unroll
    for (int i = 0; i < TM; i++)
#pragma unroll
        for (int j = 0; j < TN; j++) acc[i][j] = 0.0f;

    for (int k0 = 0; k0 < K; k0 += BK) {
#pragma unroll
        for (int r = 0; r < BM; r += 64) {
            float4 va = *(const float4*)&A[(size_t)(bm + lrow + r) * K + k0 + lcol];
            As[lcol + 0][lrow + r] = va.x;
            As[lcol + 1][lrow + r] = va.y;
            As[lcol + 2][lrow + r] = va.z;
            As[lcol + 3][lrow + r] = va.w;
        }
#pragma unroll
        for (int r = 0; r < BN; r += 64) {
            float4 vb = *(const float4*)&Bw[(size_t)(bn + lrow + r) * K + k0 + lcol];
            Bs[lcol + 0][lrow + r] = vb.x;
            Bs[lcol + 1][lrow + r] = vb.y;
            Bs[lcol + 2][lrow + r] = vb.z;
            Bs[lcol + 3][lrow + r] = vb.w;
        }
        __syncthreads();

#pragma unroll
        for (int kk = 0; kk < BK; kk++) {
            float a[TM], b[TN];
            *(float4*)&a[0] = *(const float4*)&As[kk][ty * TM];
            *(float4*)&a[4] = *(const float4*)&As[kk][ty * TM + 4];
            *(float4*)&b[0] = *(const float4*)&Bs[kk][tx * TN];
            *(float4*)&b[4] = *(const float4*)&Bs[kk][tx * TN + 4];
#pragma unroll
            for (int i = 0; i < TM; i++)
#pragma unroll
                for (int j = 0; j < TN; j++)
                    acc[i][j] = fmaf(a[i], b[j], acc[i][j]);
        }
        __syncthreads();
    }

#pragma unroll
    for (int i = 0; i < TM; i++) {
        float* crow = &C[(size_t)(bm + ty * TM + i) * N + bn + tx * TN];
        *(float4*)&crow[0] = make_float4(acc[i][0], acc[i][1], acc[i][2], acc[i][3]);
        *(float4*)&crow[4] = make_float4(acc[i][4], acc[i][5], acc[i][6], acc[i][7]);
    }
}

__global__ void __launch_bounds__(256) k_gemm_qkv(const float* __restrict__ x,
                                                  const float* __restrict__ w_qkv)
{
    gemm_tn<128, 128, 16, 8, 8>(x, w_qkv, g_qkv, MTOK, 3 * DM_, DM_);
}

__global__ void __launch_bounds__(256) k_gemm_out(const float* __restrict__ w_o,
                                                  float* __restrict__ out)
{
    gemm_tn<128, 128, 16, 8, 8>(g_ao, w_o, out, MTOK, DM_, DM_);
}

// ---------------- RoPE + split + head transpose ----------------
// one thread per (b, h, s, pair i in 0..31)
__global__ void __launch_bounds__(256) k_rope(const int* __restrict__ tp)
{
    int idx = blockIdx.x * blockDim.x + threadIdx.x;   // < 2^21
    int i = idx & 31;
    int s = (idx >> 5) & (S_ - 1);
    int h = (idx >> 16) & (H_ - 1);
    int b = idx >> 20;

    const int m = b * S_ + s;
    const float* base = g_qkv + (size_t)m * (3 * DM_) + h * DH_;

    float pos = (float)tp[s];
    float inv = powf(10000.0f, -(float)i * (1.0f / 32.0f));
    float ang = pos * inv;
    float sn, cs;
    sincosf(ang, &sn, &cs);

    size_t o = ((size_t)(b * H_ + h) * S_ + s) * DH_ + 2 * i;

    float qe = base[2 * i],            qo = base[2 * i + 1];
    float ke = base[DM_ + 2 * i],      ko = base[DM_ + 2 * i + 1];
    float ve = base[2 * DM_ + 2 * i],  vo = base[2 * DM_ + 2 * i + 1];

    g_q[o]     = qe * cs - qo * sn;
    g_q[o + 1] = qo * cs + qe * sn;
    g_k[o]     = ke * cs - ko * sn;
    g_k[o + 1] = ko * cs + ke * sn;
    g_v[o]     = ve;
    g_v[o + 1] = vo;
}

// ---------------- causal flash attention (fp32) ----------------
// grid: (S/128, B*H), block: 128 threads, 1 thread = 1 query row.
__global__ void __launch_bounds__(128) k_attn()
{
    const int bh  = blockIdx.y;
    const int q0  = blockIdx.x * 128;
    const int tid = threadIdx.x;
    const int qrow = q0 + tid;

    const float* Q = g_q + (size_t)bh * S_ * DH_;
    const float* K = g_k + (size_t)bh * S_ * DH_;
    const float* V = g_v + (size_t)bh * S_ * DH_;

    __shared__ float Ks[32][DH_];
    __shared__ float Vs[32][DH_];

    float q[DH_], o[DH_];
#pragma unroll
    for (int d = 0; d < DH_; d++) {
        q[d] = Q[(size_t)qrow * DH_ + d];
        o[d] = 0.0f;
    }
    float mrow = -INFINITY, l = 0.0f;

    for (int kt = 0; kt < q0 + 128; kt += 32) {
        const float4* kp  = (const float4*)(K + (size_t)kt * DH_);
        const float4* vp  = (const float4*)(V + (size_t)kt * DH_);
        float4* ks4 = (float4*)&Ks[0][0];
        float4* vs4 = (float4*)&Vs[0][0];
        __syncthreads();
#pragma unroll
        for (int i = 0; i < 4; i++) {
            ks4[tid + 128 * i] = kp[tid + 128 * i];
            vs4[tid + 128 * i] = vp[tid + 128 * i];
        }
        __syncthreads();

        float s[32];
#pragma unroll
        for (int j = 0; j < 32; j++) {
            float a0 = 0.f, a1 = 0.f, a2 = 0.f, a3 = 0.f;
#pragma unroll
            for (int d = 0; d < DH_; d += 4) {
                a0 = fmaf(q[d + 0], Ks[j][d + 0], a0);
                a1 = fmaf(q[d + 1], Ks[j][d + 1], a1);
                a2 = fmaf(q[d + 2], Ks[j][d + 2], a2);
                a3 = fmaf(q[d + 3], Ks[j][d + 3], a3);
            }
            float sv = ((a0 + a1) + (a2 + a3)) * 0.125f;   // * HEAD_DIM^-0.5
            s[j] = (kt + j <= qrow) ? sv : -INFINITY;
        }

        float mt = mrow;
#pragma unroll
        for (int j = 0; j < 32; j++) mt = fmaxf(mt, s[j]);

        float scale = __expf(mrow - mt);   // first tile: exp(-inf) = 0, fine
        mrow = mt;
        l *= scale;
#pragma unroll
        for (int d = 0; d < DH_; d++) o[d] *= scale;

#pragma unroll
        for (int j = 0; j < 32; j++) {
            float p = __expf(s[j] - mrow);
            l += p;
#pragma unroll
            for (int d = 0; d < DH_; d++)
                o[d] = fmaf(p, Vs[j][d], o[d]);
        }
    }

    const float invl = 1.0f / l;
    const int b = bh >> 4, h = bh & 15;
    float* dst = g_ao + ((size_t)(b * S_ + qrow)) * DM_ + h * DH_;
#pragma unroll
    for (int d = 0; d < DH_; d++) dst[d] = o[d] * invl;
}

// ---------------- launch ----------------
extern "C" void kernel_launch(void* const* d_in, const int* in_sizes, int n_in,
                              void* d_out, int out_size)
{
    const float* x      = (const float*)d_in[0];
    const float* w_qkv  = (const float*)d_in[1];
    const float* w_o    = (const float*)d_in[2];
    const int*   tp     = (const int*)d_in[3];
    // d_in[4] = mask flag; setup always uses causal (=1)

    // 1) QKV projection: [4096,1024] @ [3072,1024]^T -> g_qkv
    k_gemm_qkv<<<dim3(3 * DM_ / 128, MTOK / 128), 256>>>(x, w_qkv);

    // 2) RoPE + split into per-head layout
    {
        int total = B_ * H_ * S_ * 32;
        k_rope<<<total / 256, 256>>>(tp);
    }

    // 3) causal attention
    k_attn<<<dim3(S_ / 128, B_ * H_), 128>>>();

    // 4) output projection: [4096,1024] @ [1024,1024]^T -> d_out
    k_gemm_out<<<dim3(DM_ / 128, MTOK / 128), 256>>>(w_o, (float*)d_out);
}

// round 6
// speedup vs baseline: 1.2666x; 1.2666x over previous
#include <cuda_runtime.h>
#include <cuda_bf16.h>
#include <cstdint>
#include <math.h>

#define B_   2
#define S_   2048
#define H_   16
#define DH_  64
#define DM_  1024
#define MTOK (B_ * S_)        // 4096

// ---------------- scratch (no allocations allowed) ----------------
// NOTE: these are ONLY referenced from device code (host-side use of a
// __device__ symbol's address is UB and was the R4/R5 failure).
__device__ float g_qkv[(size_t)MTOK * 3 * DM_];     // 48 MB
__device__ float g_q  [(size_t)B_ * H_ * S_ * DH_]; // 16 MB
__device__ float g_k  [(size_t)B_ * H_ * S_ * DH_];
__device__ float g_v  [(size_t)B_ * H_ * S_ * DH_];
__device__ float g_ao [(size_t)MTOK * DM_];         // 16 MB

// ---------------- mma wrapper ----------------
__device__ __forceinline__ void mma16816(float* d, const uint32_t* a,
                                         uint32_t b0, uint32_t b1) {
    asm volatile(
        "mma.sync.aligned.m16n8k16.row.col.f32.bf16.bf16.f32 "
        "{%0,%1,%2,%3}, {%4,%5,%6,%7}, {%8,%9}, {%0,%1,%2,%3};"
        : "+f"(d[0]), "+f"(d[1]), "+f"(d[2]), "+f"(d[3])
        : "r"(a[0]), "r"(a[1]), "r"(a[2]), "r"(a[3]), "r"(b0), "r"(b1));
}

// ---------------- HMMA split-bf16 GEMM ----------------
// C[M,N] = A.B^T with A:[M,1024], B:[N,1024] fp32 K-major.
// fp32 tiles are split in-register into bf16 (hi, lo); accumulate
// hi.hi + hi.lo + lo.hi in fp32 (drops ~2^-32 lo.lo term).
// CTA tile 128x128, BK=32, 256 threads = 8 warps (4x2), warp tile 32x64.
#define LDAH  40                 // smem row stride in halves (64B data + 16B pad)

__device__ __forceinline__ void gemm_splitmma(const float* __restrict__ A,
                                              const float* __restrict__ Bw,
                                              float* __restrict__ C, int N)
{
    __shared__ __align__(16) __nv_bfloat16 Ah[128][LDAH];
    __shared__ __align__(16) __nv_bfloat16 Al[128][LDAH];
    __shared__ __align__(16) __nv_bfloat16 Bh[128][LDAH];
    __shared__ __align__(16) __nv_bfloat16 Bl[128][LDAH];

    const int tid  = threadIdx.x;
    const int lane = tid & 31;
    const int wid  = tid >> 5;
    const int wm   = wid & 3;          // 0..3 -> 32-row slice
    const int wn   = wid >> 2;         // 0..1 -> 64-col slice
    const int gid  = lane >> 2;        // 0..7
    const int tig  = lane & 3;         // 0..3
    const int bm   = blockIdx.y * 128;
    const int bn   = blockIdx.x * 128;

    // load coords: 128 rows x 32 floats per operand; 2 threads/row,
    // each thread: 4 float4 (16 floats)
    const int row0 = tid >> 1;                 // 0..127
    const int f0   = (tid & 1) * 4;            // first float4 index (of 8/row)

    float acc[2][8][4];
#pragma unroll
    for (int i = 0; i < 2; i++)
#pragma unroll
        for (int j = 0; j < 8; j++)
#pragma unroll
            for (int k = 0; k < 4; k++) acc[i][j][k] = 0.0f;

    float4 pa[4], pb[4];

    auto fetch = [&](int kk) {
#pragma unroll
        for (int i = 0; i < 4; i++) {
            pa[i] = *(const float4*)(A  + (size_t)(bm + row0) * DM_ + kk + (f0 + i) * 4);
            pb[i] = *(const float4*)(Bw + (size_t)(bn + row0) * DM_ + kk + (f0 + i) * 4);
        }
    };

    auto split_store = [&]() {
#pragma unroll
        for (int i = 0; i < 4; i++) {
            const int col = (f0 + i) * 4;
            float av[4] = {pa[i].x, pa[i].y, pa[i].z, pa[i].w};
            float bv[4] = {pb[i].x, pb[i].y, pb[i].z, pb[i].w};
            __nv_bfloat16 h[4], l[4], bh[4], bl[4];
#pragma unroll
            for (int e = 0; e < 4; e++) {
                h[e]  = __float2bfloat16(av[e]);
                l[e]  = __float2bfloat16(av[e] - __bfloat162float(h[e]));
                bh[e] = __float2bfloat16(bv[e]);
                bl[e] = __float2bfloat16(bv[e] - __bfloat162float(bh[e]));
            }
            *(__nv_bfloat162*)&Ah[row0][col]     = __nv_bfloat162(h[0], h[1]);
            *(__nv_bfloat162*)&Ah[row0][col + 2] = __nv_bfloat162(h[2], h[3]);
            *(__nv_bfloat162*)&Al[row0][col]     = __nv_bfloat162(l[0], l[1]);
            *(__nv_bfloat162*)&Al[row0][col + 2] = __nv_bfloat162(l[2], l[3]);
            *(__nv_bfloat162*)&Bh[row0][col]     = __nv_bfloat162(bh[0], bh[1]);
            *(__nv_bfloat162*)&Bh[row0][col + 2] = __nv_bfloat162(bh[2], bh[3]);
            *(__nv_bfloat162*)&Bl[row0][col]     = __nv_bfloat162(bl[0], bl[1]);
            *(__nv_bfloat162*)&Bl[row0][col + 2] = __nv_bfloat162(bl[2], bl[3]);
        }
    };

    fetch(0);

    const int NCHK = DM_ / 32;           // 32 K-chunks
    for (int c = 0; c < NCHK; c++) {
        split_store();
        __syncthreads();

        if (c + 1 < NCHK) fetch((c + 1) * 32);   // overlap LDG with MMAs

#pragma unroll
        for (int ks = 0; ks < 2; ks++) {
            const int kb = ks * 16 + tig * 2;    // fragment k base (halves)

            uint32_t ah[2][4], al[2][4];
#pragma unroll
            for (int mi = 0; mi < 2; mi++) {
                const int r = wm * 32 + mi * 16 + gid;
                ah[mi][0] = *(const uint32_t*)&Ah[r][kb];
                ah[mi][1] = *(const uint32_t*)&Ah[r + 8][kb];
                ah[mi][2] = *(const uint32_t*)&Ah[r][kb + 8];
                ah[mi][3] = *(const uint32_t*)&Ah[r + 8][kb + 8];
                al[mi][0] = *(const uint32_t*)&Al[r][kb];
                al[mi][1] = *(const uint32_t*)&Al[r + 8][kb];
                al[mi][2] = *(const uint32_t*)&Al[r][kb + 8];
                al[mi][3] = *(const uint32_t*)&Al[r + 8][kb + 8];
            }
#pragma unroll
            for (int ng = 0; ng < 8; ng++) {
                const int rn = wn * 64 + ng * 8 + gid;
                uint32_t bh0 = *(const uint32_t*)&Bh[rn][kb];
                uint32_t bh1 = *(const uint32_t*)&Bh[rn][kb + 8];
                uint32_t bl0 = *(const uint32_t*)&Bl[rn][kb];
                uint32_t bl1 = *(const uint32_t*)&Bl[rn][kb + 8];
                mma16816(acc[0][ng], ah[0], bh0, bh1);
                mma16816(acc[1][ng], ah[1], bh0, bh1);
                mma16816(acc[0][ng], ah[0], bl0, bl1);
                mma16816(acc[1][ng], ah[1], bl0, bl1);
                mma16816(acc[0][ng], al[0], bh0, bh1);
                mma16816(acc[1][ng], al[1], bh0, bh1);
            }
        }
        __syncthreads();
    }

    // epilogue: c0/c1 at (row = gid, col = 2*tig), c2/c3 at row+8
#pragma unroll
    for (int mi = 0; mi < 2; mi++) {
        const int r = bm + wm * 32 + mi * 16 + gid;
#pragma unroll
        for (int ng = 0; ng < 8; ng++) {
            const int col = bn + wn * 64 + ng * 8 + tig * 2;
            *(float2*)&C[(size_t)r * N + col] =
                make_float2(acc[mi][ng][0], acc[mi][ng][1]);
            *(float2*)&C[(size_t)(r + 8) * N + col] =
                make_float2(acc[mi][ng][2], acc[mi][ng][3]);
        }
    }
}

// wrappers: device globals referenced ONLY here (device code) — legal addresses
__global__ void __launch_bounds__(256) k_gemm_qkv(const float* __restrict__ x,
                                                  const float* __restrict__ w_qkv)
{
    gemm_splitmma(x, w_qkv, g_qkv, 3 * DM_);
}

__global__ void __launch_bounds__(256) k_gemm_out(const float* __restrict__ w_o,
                                                  float* __restrict__ out)
{
    gemm_splitmma(g_ao, w_o, out, DM_);
}

// ---------------- RoPE + split + head transpose ----------------
__global__ void __launch_bounds__(256) k_rope(const int* __restrict__ tp)
{
    int idx = blockIdx.x * blockDim.x + threadIdx.x;   // < 2^21
    int i = idx & 31;
    int s = (idx >> 5) & (S_ - 1);
    int h = (idx >> 16) & (H_ - 1);
    int b = idx >> 20;

    const int m = b * S_ + s;
    const float* base = g_qkv + (size_t)m * (3 * DM_) + h * DH_;

    float pos = (float)tp[s];
    float inv = powf(10000.0f, -(float)i * (1.0f / 32.0f));
    float ang = pos * inv;
    float sn, cs;
    sincosf(ang, &sn, &cs);

    size_t o = ((size_t)(b * H_ + h) * S_ + s) * DH_ + 2 * i;

    float qe = base[2 * i],            qo = base[2 * i + 1];
    float ke = base[DM_ + 2 * i],      ko = base[DM_ + 2 * i + 1];
    float ve = base[2 * DM_ + 2 * i],  vo = base[2 * DM_ + 2 * i + 1];

    g_q[o]     = qe * cs - qo * sn;
    g_q[o + 1] = qo * cs + qe * sn;
    g_k[o]     = ke * cs - ko * sn;
    g_k[o + 1] = ko * cs + ke * sn;
    g_v[o]     = ve;
    g_v[o + 1] = vo;
}

// ---------------- causal flash attention (fp32) ----------------
__global__ void __launch_bounds__(128) k_attn()
{
    const int bh  = blockIdx.y;
    const int q0  = blockIdx.x * 128;
    const int tid = threadIdx.x;
    const int qrow = q0 + tid;

    const float* Q = g_q + (size_t)bh * S_ * DH_;
    const float* K = g_k + (size_t)bh * S_ * DH_;
    const float* V = g_v + (size_t)bh * S_ * DH_;

    __shared__ float Ks[32][DH_];
    __shared__ float Vs[32][DH_];

    float q[DH_], o[DH_];
#pragma unroll
    for (int d = 0; d < DH_; d++) {
        q[d] = Q[(size_t)qrow * DH_ + d];
        o[d] = 0.0f;
    }
    float mrow = -INFINITY, l = 0.0f;

    for (int kt = 0; kt < q0 + 128; kt += 32) {
        const float4* kp  = (const float4*)(K + (size_t)kt * DH_);
        const float4* vp  = (const float4*)(V + (size_t)kt * DH_);
        float4* ks4 = (float4*)&Ks[0][0];
        float4* vs4 = (float4*)&Vs[0][0];
        __syncthreads();
#pragma unroll
        for (int i = 0; i < 4; i++) {
            ks4[tid + 128 * i] = kp[tid + 128 * i];
            vs4[tid + 128 * i] = vp[tid + 128 * i];
        }
        __syncthreads();

        float s[32];
#pragma unroll
        for (int j = 0; j < 32; j++) {
            float a0 = 0.f, a1 = 0.f, a2 = 0.f, a3 = 0.f;
#pragma unroll
            for (int d = 0; d < DH_; d += 4) {
                a0 = fmaf(q[d + 0], Ks[j][d + 0], a0);
                a1 = fmaf(q[d + 1], Ks[j][d + 1], a1);
                a2 = fmaf(q[d + 2], Ks[j][d + 2], a2);
                a3 = fmaf(q[d + 3], Ks[j][d + 3], a3);
            }
            float sv = ((a0 + a1) + (a2 + a3)) * 0.125f;
            s[j] = (kt + j <= qrow) ? sv : -INFINITY;
        }

        float mt = mrow;
#pragma unroll
        for (int j = 0; j < 32; j++) mt = fmaxf(mt, s[j]);

        float scale = __expf(mrow - mt);
        mrow = mt;
        l *= scale;
#pragma unroll
        for (int d = 0; d < DH_; d++) o[d] *= scale;

#pragma unroll
        for (int j = 0; j < 32; j++) {
            float p = __expf(s[j] - mrow);
            l += p;
#pragma unroll
            for (int d = 0; d < DH_; d++)
                o[d] = fmaf(p, Vs[j][d], o[d]);
        }
    }

    const float invl = 1.0f / l;
    const int b = bh >> 4, h = bh & 15;
    float* dst = g_ao + ((size_t)(b * S_ + qrow)) * DM_ + h * DH_;
#pragma unroll
    for (int d = 0; d < DH_; d++) dst[d] = o[d] * invl;
}

// ---------------- launch ----------------
extern "C" void kernel_launch(void* const* d_in, const int* in_sizes, int n_in,
                              void* d_out, int out_size)
{
    const float* x      = (const float*)d_in[0];
    const float* w_qkv  = (const float*)d_in[1];
    const float* w_o    = (const float*)d_in[2];
    const int*   tp     = (const int*)d_in[3];

    // 1) QKV projection (tensor cores, fused fp32->bf16x3 split)
    k_gemm_qkv<<<dim3(3 * DM_ / 128, MTOK / 128), 256>>>(x, w_qkv);

    // 2) RoPE + split into per-head layout
    k_rope<<<(B_ * H_ * S_ * 32) / 256, 256>>>(tp);

    // 3) causal attention (fp32)
    k_attn<<<dim3(S_ / 128, B_ * H_), 128>>>();

    // 4) output projection (tensor cores)
    k_gemm_out<<<dim3(DM_ / 128, MTOK / 128), 256>>>(w_o, (float*)d_out);
}

// round 7
// speedup vs baseline: 2.7142x; 2.1429x over previous
#include <cuda_runtime.h>
#include <cuda_bf16.h>
#include <cstdint>
#include <math.h>

#define B_   2
#define S_   2048
#define H_   16
#define DH_  64
#define DM_  1024
#define MTOK (B_ * S_)        // 4096

// ---------------- scratch (device-code references ONLY) ----------------
__device__ float g_qkv[(size_t)MTOK * 3 * DM_];     // 48 MB
__device__ float g_ao [(size_t)MTOK * DM_];         // 16 MB

// bf16 hi/lo attention operands (Q has 0.125 score scale folded in)
__device__ __nv_bfloat16 g_qhi[(size_t)B_ * H_ * S_ * DH_];
__device__ __nv_bfloat16 g_qlo[(size_t)B_ * H_ * S_ * DH_];
__device__ __nv_bfloat16 g_khi[(size_t)B_ * H_ * S_ * DH_];
__device__ __nv_bfloat16 g_klo[(size_t)B_ * H_ * S_ * DH_];
__device__ __nv_bfloat16 g_vthi[(size_t)B_ * H_ * DH_ * S_];  // transposed [bh][d][s]
__device__ __nv_bfloat16 g_vtlo[(size_t)B_ * H_ * DH_ * S_];

// ---------------- mma wrapper ----------------
__device__ __forceinline__ void mma16816(float* d, const uint32_t* a,
                                         uint32_t b0, uint32_t b1) {
    asm volatile(
        "mma.sync.aligned.m16n8k16.row.col.f32.bf16.bf16.f32 "
        "{%0,%1,%2,%3}, {%4,%5,%6,%7}, {%8,%9}, {%0,%1,%2,%3};"
        : "+f"(d[0]), "+f"(d[1]), "+f"(d[2]), "+f"(d[3])
        : "r"(a[0]), "r"(a[1]), "r"(a[2]), "r"(a[3]), "r"(b0), "r"(b1));
}

__device__ __forceinline__ uint32_t pack_bf16(float x, float y) {
    __nv_bfloat162 t(__float2bfloat16(x), __float2bfloat16(y));
    return *(uint32_t*)&t;
}

// ---------------- HMMA split-bf16 GEMM (unchanged from R6, passing) -------
#define LDAH  40                 // smem row stride in halves (64B data + 16B pad)

__device__ __forceinline__ void gemm_splitmma(const float* __restrict__ A,
                                              const float* __restrict__ Bw,
                                              float* __restrict__ C, int N)
{
    __shared__ __align__(16) __nv_bfloat16 Ah[128][LDAH];
    __shared__ __align__(16) __nv_bfloat16 Al[128][LDAH];
    __shared__ __align__(16) __nv_bfloat16 Bh[128][LDAH];
    __shared__ __align__(16) __nv_bfloat16 Bl[128][LDAH];

    const int tid  = threadIdx.x;
    const int lane = tid & 31;
    const int wid  = tid >> 5;
    const int wm   = wid & 3;
    const int wn   = wid >> 2;
    const int gid  = lane >> 2;
    const int tig  = lane & 3;
    const int bm   = blockIdx.y * 128;
    const int bn   = blockIdx.x * 128;

    const int row0 = tid >> 1;
    const int f0   = (tid & 1) * 4;

    float acc[2][8][4];
#pragma unroll
    for (int i = 0; i < 2; i++)
#pragma unroll
        for (int j = 0; j < 8; j++)
#pragma unroll
            for (int k = 0; k < 4; k++) acc[i][j][k] = 0.0f;

    float4 pa[4], pb[4];

    auto fetch = [&](int kk) {
#pragma unroll
        for (int i = 0; i < 4; i++) {
            pa[i] = *(const float4*)(A  + (size_t)(bm + row0) * DM_ + kk + (f0 + i) * 4);
            pb[i] = *(const float4*)(Bw + (size_t)(bn + row0) * DM_ + kk + (f0 + i) * 4);
        }
    };

    auto split_store = [&]() {
#pragma unroll
        for (int i = 0; i < 4; i++) {
            const int col = (f0 + i) * 4;
            float av[4] = {pa[i].x, pa[i].y, pa[i].z, pa[i].w};
            float bv[4] = {pb[i].x, pb[i].y, pb[i].z, pb[i].w};
            __nv_bfloat16 h[4], l[4], bh[4], bl[4];
#pragma unroll
            for (int e = 0; e < 4; e++) {
                h[e]  = __float2bfloat16(av[e]);
                l[e]  = __float2bfloat16(av[e] - __bfloat162float(h[e]));
                bh[e] = __float2bfloat16(bv[e]);
                bl[e] = __float2bfloat16(bv[e] - __bfloat162float(bh[e]));
            }
            *(__nv_bfloat162*)&Ah[row0][col]     = __nv_bfloat162(h[0], h[1]);
            *(__nv_bfloat162*)&Ah[row0][col + 2] = __nv_bfloat162(h[2], h[3]);
            *(__nv_bfloat162*)&Al[row0][col]     = __nv_bfloat162(l[0], l[1]);
            *(__nv_bfloat162*)&Al[row0][col + 2] = __nv_bfloat162(l[2], l[3]);
            *(__nv_bfloat162*)&Bh[row0][col]     = __nv_bfloat162(bh[0], bh[1]);
            *(__nv_bfloat162*)&Bh[row0][col + 2] = __nv_bfloat162(bh[2], bh[3]);
            *(__nv_bfloat162*)&Bl[row0][col]     = __nv_bfloat162(bl[0], bl[1]);
            *(__nv_bfloat162*)&Bl[row0][col + 2] = __nv_bfloat162(bl[2], bl[3]);
        }
    };

    fetch(0);

    const int NCHK = DM_ / 32;
    for (int c = 0; c < NCHK; c++) {
        split_store();
        __syncthreads();

        if (c + 1 < NCHK) fetch((c + 1) * 32);

#pragma unroll
        for (int ks = 0; ks < 2; ks++) {
            const int kb = ks * 16 + tig * 2;

            uint32_t ah[2][4], al[2][4];
#pragma unroll
            for (int mi = 0; mi < 2; mi++) {
                const int r = wm * 32 + mi * 16 + gid;
                ah[mi][0] = *(const uint32_t*)&Ah[r][kb];
                ah[mi][1] = *(const uint32_t*)&Ah[r + 8][kb];
                ah[mi][2] = *(const uint32_t*)&Ah[r][kb + 8];
                ah[mi][3] = *(const uint32_t*)&Ah[r + 8][kb + 8];
                al[mi][0] = *(const uint32_t*)&Al[r][kb];
                al[mi][1] = *(const uint32_t*)&Al[r + 8][kb];
                al[mi][2] = *(const uint32_t*)&Al[r][kb + 8];
                al[mi][3] = *(const uint32_t*)&Al[r + 8][kb + 8];
            }
#pragma unroll
            for (int ng = 0; ng < 8; ng++) {
                const int rn = wn * 64 + ng * 8 + gid;
                uint32_t bh0 = *(const uint32_t*)&Bh[rn][kb];
                uint32_t bh1 = *(const uint32_t*)&Bh[rn][kb + 8];
                uint32_t bl0 = *(const uint32_t*)&Bl[rn][kb];
                uint32_t bl1 = *(const uint32_t*)&Bl[rn][kb + 8];
                mma16816(acc[0][ng], ah[0], bh0, bh1);
                mma16816(acc[1][ng], ah[1], bh0, bh1);
                mma16816(acc[0][ng], ah[0], bl0, bl1);
                mma16816(acc[1][ng], ah[1], bl0, bl1);
                mma16816(acc[0][ng], al[0], bh0, bh1);
                mma16816(acc[1][ng], al[1], bh0, bh1);
            }
        }
        __syncthreads();
    }

#pragma unroll
    for (int mi = 0; mi < 2; mi++) {
        const int r = bm + wm * 32 + mi * 16 + gid;
#pragma unroll
        for (int ng = 0; ng < 8; ng++) {
            const int col = bn + wn * 64 + ng * 8 + tig * 2;
            *(float2*)&C[(size_t)r * N + col] =
                make_float2(acc[mi][ng][0], acc[mi][ng][1]);
            *(float2*)&C[(size_t)(r + 8) * N + col] =
                make_float2(acc[mi][ng][2], acc[mi][ng][3]);
        }
    }
}

__global__ void __launch_bounds__(256) k_gemm_qkv(const float* __restrict__ x,
                                                  const float* __restrict__ w_qkv)
{
    gemm_splitmma(x, w_qkv, g_qkv, 3 * DM_);
}

__global__ void __launch_bounds__(256) k_gemm_out(const float* __restrict__ w_o,
                                                  float* __restrict__ out)
{
    gemm_splitmma(g_ao, w_o, out, DM_);
}

// ---------------- RoPE + bf16 hi/lo split + head layout + V transpose ------
__global__ void __launch_bounds__(256) k_rope(const int* __restrict__ tp)
{
    int idx = blockIdx.x * 256 + threadIdx.x;
    int i = idx & 31;
    int s = (idx >> 5) & (S_ - 1);
    int h = (idx >> 16) & (H_ - 1);
    int b = idx >> 20;

    const int m = b * S_ + s;
    const float* base = g_qkv + (size_t)m * (3 * DM_) + h * DH_;

    float pos = (float)tp[s];
    float inv = powf(10000.0f, -(float)i * (1.0f / 32.0f));
    float ang = pos * inv;
    float sn, cs;
    sincosf(ang, &sn, &cs);

    float qe = base[2 * i],            qo = base[2 * i + 1];
    float ke = base[DM_ + 2 * i],      ko = base[DM_ + 2 * i + 1];
    float ve = base[2 * DM_ + 2 * i],  vo = base[2 * DM_ + 2 * i + 1];

    // Q carries the 1/sqrt(64) = 0.125 score scale (exact power of 2)
    float rqe = (qe * cs - qo * sn) * 0.125f;
    float rqo = (qo * cs + qe * sn) * 0.125f;
    float rke = ke * cs - ko * sn;
    float rko = ko * cs + ke * sn;

    size_t o = ((size_t)(b * H_ + h) * S_ + s) * DH_ + 2 * i;

    __nv_bfloat16 qh0 = __float2bfloat16(rqe), qh1 = __float2bfloat16(rqo);
    __nv_bfloat16 kh0 = __float2bfloat16(rke), kh1 = __float2bfloat16(rko);
    *(__nv_bfloat162*)&g_qhi[o] = __nv_bfloat162(qh0, qh1);
    *(__nv_bfloat162*)&g_qlo[o] = __nv_bfloat162(
        __float2bfloat16(rqe - __bfloat162float(qh0)),
        __float2bfloat16(rqo - __bfloat162float(qh1)));
    *(__nv_bfloat162*)&g_khi[o] = __nv_bfloat162(kh0, kh1);
    *(__nv_bfloat162*)&g_klo[o] = __nv_bfloat162(
        __float2bfloat16(rke - __bfloat162float(kh0)),
        __float2bfloat16(rko - __bfloat162float(kh1)));

    // V transpose via smem: block = one (b,h), 8 consecutive s
    __shared__ __nv_bfloat16 svh[64][10], svl[64][10];
    const int sl = (threadIdx.x >> 5) & 7;
    __nv_bfloat16 vh0 = __float2bfloat16(ve), vh1 = __float2bfloat16(vo);
    svh[2 * i][sl]     = vh0;
    svh[2 * i + 1][sl] = vh1;
    svl[2 * i][sl]     = __float2bfloat16(ve - __bfloat162float(vh0));
    svl[2 * i + 1][sl] = __float2bfloat16(vo - __bfloat162float(vh1));
    __syncthreads();

    if (threadIdx.x < 128) {
        const int s0  = (blockIdx.x * 8) & (S_ - 1);
        const int idx0 = blockIdx.x * 256;
        const int h0  = (idx0 >> 16) & (H_ - 1);
        const int b0  = idx0 >> 20;
        const int bh  = b0 * H_ + h0;
        const int d   = threadIdx.x >> 1;
        const int sg  = (threadIdx.x & 1) * 4;

        unsigned short uh[4], ul[4];
#pragma unroll
        for (int j = 0; j < 4; j++) {
            uh[j] = *(unsigned short*)&svh[d][sg + j];
            ul[j] = *(unsigned short*)&svl[d][sg + j];
        }
        size_t vo_ = ((size_t)bh * DH_ + d) * S_ + s0 + sg;
        *(uint2*)&g_vthi[vo_] = *(uint2*)uh;
        *(uint2*)&g_vtlo[vo_] = *(uint2*)ul;
    }
}

// ---------------- HMMA flash attention (split-bf16, causal) ----------------
// grid (S/64, B*H), 128 threads = 4 warps; warp = 16 q-rows, key tiles of 64.
#define LDK 72

__global__ void __launch_bounds__(128) k_attn_mma()
{
    const int bh  = blockIdx.y;
    const int q0  = blockIdx.x * 64;
    const int tid = threadIdx.x;
    const int lane = tid & 31;
    const int w    = tid >> 5;
    const int gid  = lane >> 2;
    const int tig  = lane & 3;

    __shared__ __align__(16) __nv_bfloat16 Khi[64][LDK], Klo[64][LDK];
    __shared__ __align__(16) __nv_bfloat16 Vth[64][LDK], Vtl[64][LDK];

    const __nv_bfloat16* qhi = g_qhi + (size_t)bh * S_ * DH_;
    const __nv_bfloat16* qlo = g_qlo + (size_t)bh * S_ * DH_;
    const __nv_bfloat16* khi = g_khi + (size_t)bh * S_ * DH_;
    const __nv_bfloat16* klo = g_klo + (size_t)bh * S_ * DH_;
    const __nv_bfloat16* vth = g_vthi + (size_t)bh * DH_ * S_;
    const __nv_bfloat16* vtl = g_vtlo + (size_t)bh * DH_ * S_;

    const int row0 = tid >> 1;            // 0..63
    const int seg0 = (tid & 1) * 4;       // 0 or 4 (of 8 16B segs per row)

    // ---- stage Q tile (reuse K smem), extract fragments ----
#pragma unroll
    for (int i2 = 0; i2 < 4; i2++) {
        *(uint4*)&Khi[row0][(seg0 + i2) * 8] =
            *(const uint4*)(qhi + (size_t)(q0 + row0) * DH_ + (seg0 + i2) * 8);
        *(uint4*)&Klo[row0][(seg0 + i2) * 8] =
            *(const uint4*)(qlo + (size_t)(q0 + row0) * DH_ + (seg0 + i2) * 8);
    }
    __syncthreads();

    uint32_t qh[4][4], ql[4][4];
    const int r = w * 16 + gid;
#pragma unroll
    for (int kb = 0; kb < 4; kb++) {
        const int kbase = kb * 16 + tig * 2;
        qh[kb][0] = *(const uint32_t*)&Khi[r][kbase];
        qh[kb][1] = *(const uint32_t*)&Khi[r + 8][kbase];
        qh[kb][2] = *(const uint32_t*)&Khi[r][kbase + 8];
        qh[kb][3] = *(const uint32_t*)&Khi[r + 8][kbase + 8];
        ql[kb][0] = *(const uint32_t*)&Klo[r][kbase];
        ql[kb][1] = *(const uint32_t*)&Klo[r + 8][kbase];
        ql[kb][2] = *(const uint32_t*)&Klo[r][kbase + 8];
        ql[kb][3] = *(const uint32_t*)&Klo[r + 8][kbase + 8];
    }
    __syncthreads();

    float o[8][4];
#pragma unroll
    for (int j = 0; j < 8; j++)
#pragma unroll
        for (int c = 0; c < 4; c++) o[j][c] = 0.0f;
    float m0 = -INFINITY, m1 = -INFINITY, l0 = 0.0f, l1 = 0.0f;

    const int r0a = q0 + w * 16 + gid;    // absolute q row for c0/c1

    for (int kt = 0; kt <= q0; kt += 64) {
        // ---- load K and V^T tiles ----
#pragma unroll
        for (int i2 = 0; i2 < 4; i2++) {
            const int sg = (seg0 + i2) * 8;
            *(uint4*)&Khi[row0][sg] =
                *(const uint4*)(khi + (size_t)(kt + row0) * DH_ + sg);
            *(uint4*)&Klo[row0][sg] =
                *(const uint4*)(klo + (size_t)(kt + row0) * DH_ + sg);
            *(uint4*)&Vth[row0][sg] =
                *(const uint4*)(vth + (size_t)row0 * S_ + kt + sg);
            *(uint4*)&Vtl[row0][sg] =
                *(const uint4*)(vtl + (size_t)row0 * S_ + kt + sg);
        }
        __syncthreads();

        // ---- scores: S = Qhi.Khi + Qhi.Klo + Qlo.Khi ----
        float s[8][4];
#pragma unroll
        for (int j = 0; j < 8; j++)
#pragma unroll
            for (int c = 0; c < 4; c++) s[j][c] = 0.0f;

#pragma unroll
        for (int kb = 0; kb < 4; kb++) {
            const int kbase = kb * 16 + tig * 2;
#pragma unroll
            for (int j = 0; j < 8; j++) {
                const int rn = j * 8 + gid;
                uint32_t kh0 = *(const uint32_t*)&Khi[rn][kbase];
                uint32_t kh1 = *(const uint32_t*)&Khi[rn][kbase + 8];
                uint32_t kl0 = *(const uint32_t*)&Klo[rn][kbase];
                uint32_t kl1 = *(const uint32_t*)&Klo[rn][kbase + 8];
                mma16816(s[j], qh[kb], kh0, kh1);
                mma16816(s[j], qh[kb], kl0, kl1);
                mma16816(s[j], ql[kb], kh0, kh1);
            }
        }

        // ---- causal mask (only the diagonal block can violate) ----
        if (kt == q0) {
#pragma unroll
            for (int j = 0; j < 8; j++) {
                const int cb = kt + j * 8 + 2 * tig;
                if (cb     > r0a)     s[j][0] = -INFINITY;
                if (cb + 1 > r0a)     s[j][1] = -INFINITY;
                if (cb     > r0a + 8) s[j][2] = -INFINITY;
                if (cb + 1 > r0a + 8) s[j][3] = -INFINITY;
            }
        }

        // ---- online softmax ----
        float tm0 = m0, tm1 = m1;
#pragma unroll
        for (int j = 0; j < 8; j++) {
            tm0 = fmaxf(tm0, fmaxf(s[j][0], s[j][1]));
            tm1 = fmaxf(tm1, fmaxf(s[j][2], s[j][3]));
        }
        tm0 = fmaxf(tm0, __shfl_xor_sync(0xffffffff, tm0, 1));
        tm0 = fmaxf(tm0, __shfl_xor_sync(0xffffffff, tm0, 2));
        tm1 = fmaxf(tm1, __shfl_xor_sync(0xffffffff, tm1, 1));
        tm1 = fmaxf(tm1, __shfl_xor_sync(0xffffffff, tm1, 2));

        const float sc0 = __expf(m0 - tm0);
        const float sc1 = __expf(m1 - tm1);
        m0 = tm0; m1 = tm1;
        l0 *= sc0; l1 *= sc1;
#pragma unroll
        for (int j = 0; j < 8; j++) {
            o[j][0] *= sc0; o[j][1] *= sc0;
            o[j][2] *= sc1; o[j][3] *= sc1;
        }

        float rs0 = 0.0f, rs1 = 0.0f;
#pragma unroll
        for (int j = 0; j < 8; j++) {
            s[j][0] = __expf(s[j][0] - m0);
            s[j][1] = __expf(s[j][1] - m0);
            s[j][2] = __expf(s[j][2] - m1);
            s[j][3] = __expf(s[j][3] - m1);
            rs0 += s[j][0] + s[j][1];
            rs1 += s[j][2] + s[j][3];
        }
        rs0 += __shfl_xor_sync(0xffffffff, rs0, 1);
        rs0 += __shfl_xor_sync(0xffffffff, rs0, 2);
        rs1 += __shfl_xor_sync(0xffffffff, rs1, 1);
        rs1 += __shfl_xor_sync(0xffffffff, rs1, 2);
        l0 += rs0; l1 += rs1;

        // ---- pack P into A-fragments (hi/lo), acc->frag layout identity ----
        uint32_t ph[4][4], pl[4][4];
#pragma unroll
        for (int kb = 0; kb < 4; kb++) {
            const int j0 = 2 * kb, j1 = 2 * kb + 1;
            ph[kb][0] = pack_bf16(s[j0][0], s[j0][1]);
            ph[kb][1] = pack_bf16(s[j0][2], s[j0][3]);
            ph[kb][2] = pack_bf16(s[j1][0], s[j1][1]);
            ph[kb][3] = pack_bf16(s[j1][2], s[j1][3]);
            __nv_bfloat162 h0 = *(__nv_bfloat162*)&ph[kb][0];
            __nv_bfloat162 h1 = *(__nv_bfloat162*)&ph[kb][1];
            __nv_bfloat162 h2 = *(__nv_bfloat162*)&ph[kb][2];
            __nv_bfloat162 h3 = *(__nv_bfloat162*)&ph[kb][3];
            pl[kb][0] = pack_bf16(s[j0][0] - __bfloat162float(h0.x),
                                  s[j0][1] - __bfloat162float(h0.y));
            pl[kb][1] = pack_bf16(s[j0][2] - __bfloat162float(h1.x),
                                  s[j0][3] - __bfloat162float(h1.y));
            pl[kb][2] = pack_bf16(s[j1][0] - __bfloat162float(h2.x),
                                  s[j1][1] - __bfloat162float(h2.y));
            pl[kb][3] = pack_bf16(s[j1][2] - __bfloat162float(h3.x),
                                  s[j1][3] - __bfloat162float(h3.y));
        }

        // ---- O += P.V : Phi.Vhi + Phi.Vlo + Plo.Vhi ----
#pragma unroll
        for (int kb = 0; kb < 4; kb++) {
            const int kbase = kb * 16 + tig * 2;
#pragma unroll
            for (int j = 0; j < 8; j++) {
                const int rn = j * 8 + gid;
                uint32_t vh0 = *(const uint32_t*)&Vth[rn][kbase];
                uint32_t vh1 = *(const uint32_t*)&Vth[rn][kbase + 8];
                uint32_t vl0 = *(const uint32_t*)&Vtl[rn][kbase];
                uint32_t vl1 = *(const uint32_t*)&Vtl[rn][kbase + 8];
                mma16816(o[j], ph[kb], vh0, vh1);
                mma16816(o[j], ph[kb], vl0, vl1);
                mma16816(o[j], pl[kb], vh0, vh1);
            }
        }
        __syncthreads();
    }

    // ---- epilogue ----
    const float inv0 = 1.0f / l0;
    const float inv1 = 1.0f / l1;
    const int b = bh >> 4, h = bh & 15;
#pragma unroll
    for (int j = 0; j < 8; j++) {
        const int col = h * DH_ + j * 8 + 2 * tig;
        *(float2*)&g_ao[(size_t)(b * S_ + r0a) * DM_ + col] =
            make_float2(o[j][0] * inv0, o[j][1] * inv0);
        *(float2*)&g_ao[(size_t)(b * S_ + r0a + 8) * DM_ + col] =
            make_float2(o[j][2] * inv1, o[j][3] * inv1);
    }
}

// ---------------- launch ----------------
extern "C" void kernel_launch(void* const* d_in, const int* in_sizes, int n_in,
                              void* d_out, int out_size)
{
    const float* x      = (const float*)d_in[0];
    const float* w_qkv  = (const float*)d_in[1];
    const float* w_o    = (const float*)d_in[2];
    const int*   tp     = (const int*)d_in[3];

    // 1) QKV projection (HMMA, fused fp32->bf16x3 split)
    k_gemm_qkv<<<dim3(3 * DM_ / 128, MTOK / 128), 256>>>(x, w_qkv);

    // 2) RoPE + bf16 hi/lo per-head layout + V transpose
    k_rope<<<(B_ * H_ * S_ * 32) / 256, 256>>>(tp);

    // 3) causal flash attention (HMMA split-bf16)
    k_attn_mma<<<dim3(S_ / 64, B_ * H_), 128>>>();

    // 4) output projection (HMMA)
    k_gemm_out<<<dim3(DM_ / 128, MTOK / 128), 256>>>(w_o, (float*)d_out);
}